// round 4
// baseline (speedup 1.0000x reference)
#include <cuda_runtime.h>

#define N_NODES  500000
#define N_EDGES  8000000
#define N_GRAPHS 4096
#define IN_DIM   9
#define HID      64
#define PAD      12   // padded row: 9 real + 3 zero, 48B (16B-aligned rows)

// Scratch (static device globals — no allocation in kernel_launch)
__device__ float g_xp [N_NODES * PAD];   // padded copy of x (gather source)
__device__ float g_agg[N_NODES * PAD];   // aggregation buffer, init = x  (=> agg + x for free)
__device__ float g_acc[N_GRAPHS];        // per-graph scalar accumulator
__device__ float g_v  [HID];             // v = w2 @ w3
__device__ float g_c;                    // c = b2 . w3
__device__ int   g_w64;                  // 1 if indices are int64, 0 if int32

// ---------------------------------------------------------------------------
// detect: probe edge_index dtype. If int64, every odd int32 word (high half)
// is 0 since indices < 500000. Reading 32 int32 words is in-bounds either way.
// ---------------------------------------------------------------------------
__global__ void detect_kernel(const int* __restrict__ ei32)
{
    int nz = 0;
    #pragma unroll
    for (int k = 0; k < 16; k++) nz |= ei32[2 * k + 1];
    g_w64 = (nz == 0) ? 1 : 0;
}

// ---------------------------------------------------------------------------
// prep: zero per-graph accumulators, fold w2@w3 and b2.w3
// ---------------------------------------------------------------------------
__global__ void prep_kernel(const float* __restrict__ w2,
                            const float* __restrict__ b2,
                            const float* __restrict__ w3)
{
    int t = blockIdx.x * blockDim.x + threadIdx.x;
    if (t < N_GRAPHS) g_acc[t] = 0.0f;
    if (t < HID) {
        float a = 0.0f;
        #pragma unroll
        for (int j = 0; j < HID; j++) a = fmaf(w2[t * HID + j], w3[j], a);
        g_v[t] = a;
    }
    if (t == 0) {
        float a = 0.0f;
        for (int j = 0; j < HID; j++) a = fmaf(b2[j], w3[j], a);
        g_c = a;
    }
}

// ---------------------------------------------------------------------------
// pad: xp[i] = pad12(x[i]);  agg[i] = pad12(x[i])   (agg starts at x)
// ---------------------------------------------------------------------------
__global__ void pad_kernel(const float* __restrict__ x)
{
    int i = blockIdx.x * blockDim.x + threadIdx.x;
    if (i >= N_NODES) return;
    float r[PAD];
    #pragma unroll
    for (int k = 0; k < IN_DIM; k++) r[k] = x[i * IN_DIM + k];
    #pragma unroll
    for (int k = IN_DIM; k < PAD; k++) r[k] = 0.0f;
    float4* xp = reinterpret_cast<float4*>(g_xp  + (size_t)i * PAD);
    float4* ag = reinterpret_cast<float4*>(g_agg + (size_t)i * PAD);
    #pragma unroll
    for (int k = 0; k < 3; k++) {
        float4 v = make_float4(r[4*k], r[4*k+1], r[4*k+2], r[4*k+3]);
        xp[k] = v;
        ag[k] = v;
    }
}

// ---------------------------------------------------------------------------
// edge scatter: agg[dst] += x[src]  (vector REDs, 4 edges per thread)
// ---------------------------------------------------------------------------
__global__ void edge_kernel(const void* __restrict__ eiv)
{
    int t  = blockIdx.x * blockDim.x + threadIdx.x;
    int e0 = t * 4;
    if (e0 >= N_EDGES) return;

    int ss[4], dd[4];
    if (g_w64) {
        const long long* ei = (const long long*)eiv;
        longlong2 s01 = *reinterpret_cast<const longlong2*>(ei + e0);
        longlong2 s23 = *reinterpret_cast<const longlong2*>(ei + e0 + 2);
        longlong2 d01 = *reinterpret_cast<const longlong2*>(ei + N_EDGES + e0);
        longlong2 d23 = *reinterpret_cast<const longlong2*>(ei + N_EDGES + e0 + 2);
        ss[0] = (int)s01.x; ss[1] = (int)s01.y; ss[2] = (int)s23.x; ss[3] = (int)s23.y;
        dd[0] = (int)d01.x; dd[1] = (int)d01.y; dd[2] = (int)d23.x; dd[3] = (int)d23.y;
    } else {
        const int* ei = (const int*)eiv;
        int4 s = *reinterpret_cast<const int4*>(ei + e0);
        int4 d = *reinterpret_cast<const int4*>(ei + N_EDGES + e0);
        ss[0] = s.x; ss[1] = s.y; ss[2] = s.z; ss[3] = s.w;
        dd[0] = d.x; dd[1] = d.y; dd[2] = d.z; dd[3] = d.w;
    }

    #pragma unroll
    for (int k = 0; k < 4; k++) {
        const float* sp = g_xp + (size_t)ss[k] * PAD;
        const float4 a  = __ldg(reinterpret_cast<const float4*>(sp));
        const float4 b  = __ldg(reinterpret_cast<const float4*>(sp) + 1);
        const float  c8 = __ldg(sp + 8);
        float* dp = g_agg + (size_t)dd[k] * PAD;
        asm volatile("red.global.add.v4.f32 [%0], {%1,%2,%3,%4};"
                     :: "l"(dp), "f"(a.x), "f"(a.y), "f"(a.z), "f"(a.w) : "memory");
        asm volatile("red.global.add.v4.f32 [%0], {%1,%2,%3,%4};"
                     :: "l"(dp + 4), "f"(b.x), "f"(b.y), "f"(b.z), "f"(b.w) : "memory");
        asm volatile("red.global.add.f32 [%0], %1;"
                     :: "l"(dp + 8), "f"(c8) : "memory");
    }
}

// ---------------------------------------------------------------------------
// node MLP + fused readout + warp-segmented pool
//   s_i = relu((agg_i) @ w1 + b1) . v + c ;  g_acc[batch[i]] += s_i
// ---------------------------------------------------------------------------
__global__ void node_kernel(const float* __restrict__ w1,
                            const float* __restrict__ b1,
                            const void* __restrict__ batchv)
{
    __shared__ float w1s[IN_DIM * HID];
    __shared__ float b1s[HID];
    __shared__ float vs [HID];

    int tid = threadIdx.x;
    for (int i = tid; i < IN_DIM * HID; i += blockDim.x) w1s[i] = w1[i];
    if (tid < HID) { b1s[tid] = b1[tid]; vs[tid] = g_v[tid]; }
    __syncthreads();

    int i = blockIdx.x * blockDim.x + tid;
    bool valid = (i < N_NODES);

    float s = 0.0f;
    int   g = -1;
    if (valid) {
        g = g_w64 ? (int)((const long long*)batchv)[i]
                  : ((const int*)batchv)[i];
        const float4* ap = reinterpret_cast<const float4*>(g_agg + (size_t)i * PAD);
        float4 r0 = ap[0], r1 = ap[1];
        float  r8 = g_agg[(size_t)i * PAD + 8];
        float row[9] = {r0.x, r0.y, r0.z, r0.w, r1.x, r1.y, r1.z, r1.w, r8};
        s = g_c;
        for (int j = 0; j < HID; j++) {
            float z = b1s[j];
            #pragma unroll
            for (int k = 0; k < 9; k++) z = fmaf(row[k], w1s[k * HID + j], z);
            s = fmaf(fmaxf(z, 0.0f), vs[j], s);
        }
    }

    // warp-level segmented inclusive scan over sorted graph ids
    int lane = tid & 31;
    #pragma unroll
    for (int off = 1; off < 32; off <<= 1) {
        float os = __shfl_up_sync(0xFFFFFFFFu, s, off);
        int   og = __shfl_up_sync(0xFFFFFFFFu, g, off);
        if (lane >= off && og == g) s += os;
    }
    int   ng   = __shfl_down_sync(0xFFFFFFFFu, g, 1);
    bool  last = (lane == 31) || (ng != g);
    if (valid && last) atomicAdd(&g_acc[g], s);
}

// ---------------------------------------------------------------------------
// finish: out[g] = g_acc[g] + b3[0]
// ---------------------------------------------------------------------------
__global__ void finish_kernel(float* __restrict__ out, const float* __restrict__ b3)
{
    int t = blockIdx.x * blockDim.x + threadIdx.x;
    if (t < N_GRAPHS) out[t] = g_acc[t] + b3[0];
}

// ---------------------------------------------------------------------------
extern "C" void kernel_launch(void* const* d_in, const int* in_sizes, int n_in,
                              void* d_out, int out_size)
{
    const float* x     = (const float*)d_in[0];
    const void*  ei    = d_in[1];
    const void*  batch = d_in[2];
    const float* w1    = (const float*)d_in[3];
    const float* b1    = (const float*)d_in[4];
    const float* w2    = (const float*)d_in[5];
    const float* b2    = (const float*)d_in[6];
    const float* w3    = (const float*)d_in[7];
    const float* b3    = (const float*)d_in[8];
    float*       out   = (float*)d_out;

    detect_kernel<<<1, 1>>>((const int*)ei);
    prep_kernel<<<(N_GRAPHS + 255) / 256, 256>>>(w2, b2, w3);
    pad_kernel<<<(N_NODES + 255) / 256, 256>>>(x);
    edge_kernel<<<(N_EDGES / 4 + 255) / 256, 256>>>(ei);
    node_kernel<<<(N_NODES + 255) / 256, 256>>>(w1, b1, batch);
    finish_kernel<<<(N_GRAPHS + 255) / 256, 256>>>(out, b3);
}

// round 5
// speedup vs baseline: 1.4017x; 1.4017x over previous
#include <cuda_runtime.h>
#include <cuda_fp16.h>

#define N_NODES  500000
#define N_EDGES  8000000
#define N_GRAPHS 4096
#define IN_DIM   9
#define HID      64
#define PADH     16   // halves per row: 9 real + 7 zero = 32B = one L2 sector

// Scratch (static device globals — no allocation in kernel_launch)
__device__ __align__(128) uint4 g_xh [N_NODES * 2];  // fp16 features, 32B/row
__device__ __align__(128) uint4 g_agg[N_NODES * 2];  // fp16 agg, init = x
__device__ float g_acc[N_GRAPHS];
__device__ float g_v  [HID];              // v = w2 @ w3
__device__ float g_c;                     // c = b2 . w3
__device__ int   g_w64;                   // 1 if indices are int64

// ---------------------------------------------------------------------------
// detect: probe index dtype. int64 indices < 500000 => all high words zero.
// ---------------------------------------------------------------------------
__global__ void detect_kernel(const int* __restrict__ ei32)
{
    int nz = 0;
    #pragma unroll
    for (int k = 0; k < 16; k++) nz |= ei32[2 * k + 1];
    g_w64 = (nz == 0) ? 1 : 0;
}

// ---------------------------------------------------------------------------
// prep: zero accumulators; fold w2@w3 -> v, b2.w3 -> c
// ---------------------------------------------------------------------------
__global__ void prep_kernel(const float* __restrict__ w2,
                            const float* __restrict__ b2,
                            const float* __restrict__ w3)
{
    int t = blockIdx.x * blockDim.x + threadIdx.x;
    if (t < N_GRAPHS) g_acc[t] = 0.0f;
    if (t < HID) {
        float a = 0.0f;
        #pragma unroll
        for (int j = 0; j < HID; j++) a = fmaf(w2[t * HID + j], w3[j], a);
        g_v[t] = a;
    }
    if (t == 0) {
        float a = 0.0f;
        for (int j = 0; j < HID; j++) a = fmaf(b2[j], w3[j], a);
        g_c = a;
    }
}

// ---------------------------------------------------------------------------
// pad: convert x row (9 f32) -> 16 halves; write to g_xh and g_agg (init=x)
// ---------------------------------------------------------------------------
__global__ void pad_kernel(const float* __restrict__ x)
{
    int i = blockIdx.x * blockDim.x + threadIdx.x;
    if (i >= N_NODES) return;
    unsigned u[8];
    #pragma unroll
    for (int k = 0; k < 8; k++) u[k] = 0u;
    #pragma unroll
    for (int k = 0; k < IN_DIM; k++) {
        unsigned h = (unsigned)__half_as_ushort(__float2half_rn(x[i * IN_DIM + k]));
        u[k >> 1] |= h << ((k & 1) * 16);
    }
    uint4 lo = make_uint4(u[0], u[1], u[2], u[3]);
    uint4 hi = make_uint4(u[4], u[5], u[6], u[7]);
    g_xh [i * 2 + 0] = lo;  g_xh [i * 2 + 1] = hi;
    g_agg[i * 2 + 0] = lo;  g_agg[i * 2 + 1] = hi;
}

// ---------------------------------------------------------------------------
// edge scatter: agg[dst] += x[src], fp16, one sector in / one sector out
// ---------------------------------------------------------------------------
__global__ void edge_kernel(const void* __restrict__ eiv)
{
    int t  = blockIdx.x * blockDim.x + threadIdx.x;
    int e0 = t * 4;
    if (e0 >= N_EDGES) return;

    int ss[4], dd[4];
    if (g_w64) {
        const long long* ei = (const long long*)eiv;
        longlong2 s01 = *reinterpret_cast<const longlong2*>(ei + e0);
        longlong2 s23 = *reinterpret_cast<const longlong2*>(ei + e0 + 2);
        longlong2 d01 = *reinterpret_cast<const longlong2*>(ei + N_EDGES + e0);
        longlong2 d23 = *reinterpret_cast<const longlong2*>(ei + N_EDGES + e0 + 2);
        ss[0] = (int)s01.x; ss[1] = (int)s01.y; ss[2] = (int)s23.x; ss[3] = (int)s23.y;
        dd[0] = (int)d01.x; dd[1] = (int)d01.y; dd[2] = (int)d23.x; dd[3] = (int)d23.y;
    } else {
        const int* ei = (const int*)eiv;
        int4 s = *reinterpret_cast<const int4*>(ei + e0);
        int4 d = *reinterpret_cast<const int4*>(ei + N_EDGES + e0);
        ss[0] = s.x; ss[1] = s.y; ss[2] = s.z; ss[3] = s.w;
        dd[0] = d.x; dd[1] = d.y; dd[2] = d.z; dd[3] = d.w;
    }

    #pragma unroll
    for (int k = 0; k < 4; k++) {
        const uint4* sp = &g_xh[(size_t)ss[k] * 2];
        uint4 a = __ldg(sp);
        uint4 b = __ldg(sp + 1);
        uint4* dp = &g_agg[(size_t)dd[k] * 2];
        asm volatile("red.global.add.noftz.v4.f16x2 [%0], {%1,%2,%3,%4};"
                     :: "l"(dp),     "r"(a.x), "r"(a.y), "r"(a.z), "r"(a.w) : "memory");
        asm volatile("red.global.add.noftz.v4.f16x2 [%0], {%1,%2,%3,%4};"
                     :: "l"(dp + 1), "r"(b.x), "r"(b.y), "r"(b.z), "r"(b.w) : "memory");
    }
}

// ---------------------------------------------------------------------------
// node MLP + fused readout + warp-segmented pool
//   s_i = relu(agg_i @ w1 + b1) . v + c ;  g_acc[batch[i]] += s_i
// ---------------------------------------------------------------------------
__global__ void node_kernel(const float* __restrict__ w1,
                            const float* __restrict__ b1,
                            const void* __restrict__ batchv)
{
    __shared__ float w1s[IN_DIM * HID];
    __shared__ float b1s[HID];
    __shared__ float vs [HID];

    int tid = threadIdx.x;
    for (int i = tid; i < IN_DIM * HID; i += blockDim.x) w1s[i] = w1[i];
    if (tid < HID) { b1s[tid] = b1[tid]; vs[tid] = g_v[tid]; }
    __syncthreads();

    int i = blockIdx.x * blockDim.x + tid;
    bool valid = (i < N_NODES);

    float s = 0.0f;
    int   g = -1;
    if (valid) {
        g = g_w64 ? (int)((const long long*)batchv)[i]
                  : ((const int*)batchv)[i];
        uint4 lo = g_agg[(size_t)i * 2];
        uint4 hi = g_agg[(size_t)i * 2 + 1];
        unsigned u[5] = {lo.x, lo.y, lo.z, lo.w, hi.x};
        float row[9];
        #pragma unroll
        for (int k = 0; k < 4; k++) {
            float2 f = __half22float2(*reinterpret_cast<__half2*>(&u[k]));
            row[2 * k]     = f.x;
            row[2 * k + 1] = f.y;
        }
        row[8] = __half2float(__ushort_as_half((unsigned short)(u[4] & 0xFFFF)));

        s = g_c;
        for (int j = 0; j < HID; j++) {
            float z = b1s[j];
            #pragma unroll
            for (int k = 0; k < 9; k++) z = fmaf(row[k], w1s[k * HID + j], z);
            s = fmaf(fmaxf(z, 0.0f), vs[j], s);
        }
    }

    // warp-level segmented inclusive scan over sorted graph ids
    int lane = tid & 31;
    #pragma unroll
    for (int off = 1; off < 32; off <<= 1) {
        float os = __shfl_up_sync(0xFFFFFFFFu, s, off);
        int   og = __shfl_up_sync(0xFFFFFFFFu, g, off);
        if (lane >= off && og == g) s += os;
    }
    int   ng   = __shfl_down_sync(0xFFFFFFFFu, g, 1);
    bool  last = (lane == 31) || (ng != g);
    if (valid && last) atomicAdd(&g_acc[g], s);
}

// ---------------------------------------------------------------------------
__global__ void finish_kernel(float* __restrict__ out, const float* __restrict__ b3)
{
    int t = blockIdx.x * blockDim.x + threadIdx.x;
    if (t < N_GRAPHS) out[t] = g_acc[t] + b3[0];
}

// ---------------------------------------------------------------------------
extern "C" void kernel_launch(void* const* d_in, const int* in_sizes, int n_in,
                              void* d_out, int out_size)
{
    const float* x     = (const float*)d_in[0];
    const void*  ei    = d_in[1];
    const void*  batch = d_in[2];
    const float* w1    = (const float*)d_in[3];
    const float* b1    = (const float*)d_in[4];
    const float* w2    = (const float*)d_in[5];
    const float* b2    = (const float*)d_in[6];
    const float* w3    = (const float*)d_in[7];
    const float* b3    = (const float*)d_in[8];
    float*       out   = (float*)d_out;

    detect_kernel<<<1, 1>>>((const int*)ei);
    prep_kernel<<<(N_GRAPHS + 255) / 256, 256>>>(w2, b2, w3);
    pad_kernel<<<(N_NODES + 255) / 256, 256>>>(x);
    edge_kernel<<<(N_EDGES / 4 + 255) / 256, 256>>>(ei);
    node_kernel<<<(N_NODES + 255) / 256, 256>>>(w1, b1, batch);
    finish_kernel<<<(N_GRAPHS + 255) / 256, 256>>>(out, b3);
}

// round 7
// speedup vs baseline: 1.4053x; 1.0026x over previous
#include <cuda_runtime.h>
#include <cuda_fp16.h>

#define N_NODES  500000
#define N_EDGES  8000000
#define N_GRAPHS 4096
#define IN_DIM   9
#define HID      64

typedef unsigned long long u64;

// Scratch (static device globals — no allocation in kernel_launch)
__device__ __align__(128) uint4 g_xh [N_NODES * 2];  // fp16 features, 32B/row
__device__ __align__(128) uint4 g_agg[N_NODES * 2];  // fp16 agg, init = x
__device__ float g_acc[N_GRAPHS];
__device__ float g_v  [HID];              // v = w2 @ w3
__device__ float g_c;                     // c = b2 . w3
__device__ int   g_w64;                   // 1 if indices are int64
__device__ unsigned g_done;               // last-block counter for fused finish

// ---- packed f32x2 helpers (sm_103a FFMA2; only reachable via PTX) ----
__device__ __forceinline__ u64 pack2(float lo, float hi) {
    u64 r; asm("mov.b64 %0, {%1, %2};" : "=l"(r) : "f"(lo), "f"(hi)); return r;
}
__device__ __forceinline__ void unpack2(u64 v, float& lo, float& hi) {
    asm("mov.b64 {%0, %1}, %2;" : "=f"(lo), "=f"(hi) : "l"(v));
}
__device__ __forceinline__ u64 fma2(u64 a, u64 b, u64 c) {
    u64 d; asm("fma.rn.f32x2 %0, %1, %2, %3;" : "=l"(d) : "l"(a), "l"(b), "l"(c));
    return d;
}

// ---------------------------------------------------------------------------
// pad_all: fused detect + prep + pad
//   - convert x rows (9 f32) -> 16 halves into g_xh and g_agg (agg init = x)
//   - zero g_acc, g_done; fold w2@w3 -> g_v, b2.w3 -> g_c; detect index dtype
// ---------------------------------------------------------------------------
__global__ void pad_all_kernel(const float* __restrict__ x,
                               const float* __restrict__ w2,
                               const float* __restrict__ b2,
                               const float* __restrict__ w3,
                               const int*   __restrict__ ei32)
{
    int t = blockIdx.x * blockDim.x + threadIdx.x;

    // --- prep side (first few blocks) ---
    if (t < N_GRAPHS) g_acc[t] = 0.0f;
    if (t < HID) {
        float a = 0.0f;
        #pragma unroll
        for (int j = 0; j < HID; j++) a = fmaf(w2[t * HID + j], w3[j], a);
        g_v[t] = a;
    }
    if (t == 0) {
        float a = 0.0f;
        for (int j = 0; j < HID; j++) a = fmaf(b2[j], w3[j], a);
        g_c = a;
        g_done = 0u;
        int nz = 0;
        #pragma unroll
        for (int k = 0; k < 16; k++) nz |= ei32[2 * k + 1];
        g_w64 = (nz == 0) ? 1 : 0;
    }

    // --- pad side ---
    if (t >= N_NODES) return;
    unsigned u[8];
    #pragma unroll
    for (int k = 0; k < 8; k++) u[k] = 0u;
    #pragma unroll
    for (int k = 0; k < IN_DIM; k++) {
        unsigned h = (unsigned)__half_as_ushort(__float2half_rn(x[t * IN_DIM + k]));
        u[k >> 1] |= h << ((k & 1) * 16);
    }
    uint4 lo = make_uint4(u[0], u[1], u[2], u[3]);
    uint4 hi = make_uint4(u[4], u[5], u[6], u[7]);
    g_xh [t * 2 + 0] = lo;  g_xh [t * 2 + 1] = hi;
    g_agg[t * 2 + 0] = lo;  g_agg[t * 2 + 1] = hi;
}

// ---------------------------------------------------------------------------
// edge scatter: agg[dst] += x[src]; two 128-bit vector REDs per edge
// ---------------------------------------------------------------------------
__global__ void edge_kernel(const void* __restrict__ eiv)
{
    int t  = blockIdx.x * blockDim.x + threadIdx.x;
    int e0 = t * 4;
    if (e0 >= N_EDGES) return;

    int ss[4], dd[4];
    if (g_w64) {
        const long long* ei = (const long long*)eiv;
        longlong2 s01 = *reinterpret_cast<const longlong2*>(ei + e0);
        longlong2 s23 = *reinterpret_cast<const longlong2*>(ei + e0 + 2);
        longlong2 d01 = *reinterpret_cast<const longlong2*>(ei + N_EDGES + e0);
        longlong2 d23 = *reinterpret_cast<const longlong2*>(ei + N_EDGES + e0 + 2);
        ss[0] = (int)s01.x; ss[1] = (int)s01.y; ss[2] = (int)s23.x; ss[3] = (int)s23.y;
        dd[0] = (int)d01.x; dd[1] = (int)d01.y; dd[2] = (int)d23.x; dd[3] = (int)d23.y;
    } else {
        const int* ei = (const int*)eiv;
        int4 s = *reinterpret_cast<const int4*>(ei + e0);
        int4 d = *reinterpret_cast<const int4*>(ei + N_EDGES + e0);
        ss[0] = s.x; ss[1] = s.y; ss[2] = s.z; ss[3] = s.w;
        dd[0] = d.x; dd[1] = d.y; dd[2] = d.z; dd[3] = d.w;
    }

    #pragma unroll
    for (int k = 0; k < 4; k++) {
        const uint4* sp = &g_xh[(size_t)ss[k] * 2];
        uint4 a = __ldg(sp);
        uint4 b = __ldg(sp + 1);
        uint4* dp = &g_agg[(size_t)dd[k] * 2];
        asm volatile("red.global.add.noftz.v4.f16x2 [%0], {%1,%2,%3,%4};"
                     :: "l"(dp),     "r"(a.x), "r"(a.y), "r"(a.z), "r"(a.w) : "memory");
        asm volatile("red.global.add.noftz.v4.f16x2 [%0], {%1,%2,%3,%4};"
                     :: "l"(dp + 1), "r"(b.x), "r"(b.y), "r"(b.z), "r"(b.w) : "memory");
    }
}

// ---------------------------------------------------------------------------
// node MLP + fused readout + warp-segmented pool + fused finish (last block)
//   s_i = relu(agg_i @ w1 + b1) . v + c ;  g_acc[batch[i]] += s_i
//   out[g] = g_acc[g] + b3[0]
// ---------------------------------------------------------------------------
__global__ void node_kernel(const float* __restrict__ w1,
                            const float* __restrict__ b1,
                            const void* __restrict__ batchv,
                            float* __restrict__ out,
                            const float* __restrict__ b3)
{
    __shared__ __align__(16) float w1s[IN_DIM * HID];
    __shared__ __align__(16) float b1s[HID];
    __shared__ __align__(16) float vs [HID];
    __shared__ bool s_last;

    int tid = threadIdx.x;
    for (int i = tid; i < IN_DIM * HID; i += blockDim.x) w1s[i] = w1[i];
    if (tid < HID) { b1s[tid] = b1[tid]; vs[tid] = g_v[tid]; }
    __syncthreads();

    const u64* w1p = reinterpret_cast<const u64*>(w1s);  // [9][32] pairs
    const u64* b1p = reinterpret_cast<const u64*>(b1s);  // [32]
    const u64* vp  = reinterpret_cast<const u64*>(vs);   // [32]

    int i = blockIdx.x * blockDim.x + tid;
    bool valid = (i < N_NODES);

    float s = 0.0f;
    int   g = -1;
    if (valid) {
        g = g_w64 ? (int)((const long long*)batchv)[i]
                  : ((const int*)batchv)[i];
        uint4 lo = g_agg[(size_t)i * 2];
        uint4 hi = g_agg[(size_t)i * 2 + 1];
        unsigned u[5] = {lo.x, lo.y, lo.z, lo.w, hi.x};
        u64 rowp[9];
        #pragma unroll
        for (int k = 0; k < 4; k++) {
            float2 f = __half22float2(*reinterpret_cast<__half2*>(&u[k]));
            rowp[2 * k]     = pack2(f.x, f.x);
            rowp[2 * k + 1] = pack2(f.y, f.y);
        }
        {
            float r8 = __half2float(__ushort_as_half((unsigned short)(u[4] & 0xFFFF)));
            rowp[8] = pack2(r8, r8);
        }

        u64 s2 = pack2(0.0f, 0.0f);
        #pragma unroll 4
        for (int j2 = 0; j2 < HID / 2; j2++) {
            u64 z2 = b1p[j2];
            #pragma unroll
            for (int k = 0; k < IN_DIM; k++)
                z2 = fma2(rowp[k], w1p[k * (HID / 2) + j2], z2);
            float zl, zh; unpack2(z2, zl, zh);
            s2 = fma2(pack2(fmaxf(zl, 0.0f), fmaxf(zh, 0.0f)), vp[j2], s2);
        }
        float sl, sh; unpack2(s2, sl, sh);
        s = sl + sh + g_c;
    }

    // warp-level segmented inclusive scan over sorted graph ids
    int lane = tid & 31;
    #pragma unroll
    for (int off = 1; off < 32; off <<= 1) {
        float os = __shfl_up_sync(0xFFFFFFFFu, s, off);
        int   og = __shfl_up_sync(0xFFFFFFFFu, g, off);
        if (lane >= off && og == g) s += os;
    }
    int   ng   = __shfl_down_sync(0xFFFFFFFFu, g, 1);
    bool  last = (lane == 31) || (ng != g);
    if (valid && last) atomicAdd(&g_acc[g], s);

    // fused finish: last block to retire writes the output
    __threadfence();
    __syncthreads();
    if (tid == 0) {
        unsigned prev = atomicAdd(&g_done, 1u);
        s_last = (prev == gridDim.x - 1);
    }
    __syncthreads();
    if (s_last) {
        float bias = b3[0];
        for (int t = tid; t < N_GRAPHS; t += blockDim.x) {
            float a;
            asm volatile("ld.global.acquire.gpu.b32 %0, [%1];"
                         : "=f"(a) : "l"(&g_acc[t]));
            out[t] = a + bias;
        }
    }
}

// ---------------------------------------------------------------------------
extern "C" void kernel_launch(void* const* d_in, const int* in_sizes, int n_in,
                              void* d_out, int out_size)
{
    const float* x     = (const float*)d_in[0];
    const void*  ei    = d_in[1];
    const void*  batch = d_in[2];
    const float* w1    = (const float*)d_in[3];
    const float* b1    = (const float*)d_in[4];
    const float* w2    = (const float*)d_in[5];
    const float* b2    = (const float*)d_in[6];
    const float* w3    = (const float*)d_in[7];
    const float* b3    = (const float*)d_in[8];
    float*       out   = (float*)d_out;

    pad_all_kernel<<<(N_NODES + 255) / 256, 256>>>(x, w2, b2, w3, (const int*)ei);
    edge_kernel<<<(N_EDGES / 4 + 255) / 256, 256>>>(ei);
    node_kernel<<<(N_NODES + 255) / 256, 256>>>(w1, b1, batch, out, b3);
}